// round 16
// baseline (speedup 1.0000x reference)
#include <cuda_runtime.h>

#define FULL 0xFFFFFFFFu

// Problem constants
#define BATCH 32
#define IN    2048
#define OUT   2048
#define KNUM  8
#define HDIM  512
#define KSZ   (IN * OUT)          // 4M elements per expert

#define IBLK   512                // i-range per block (8 quarters of 64)
#define NCHUNK (IN / IBLK)        // 4
#define NQ     (IBLK / 64)        // 8
#define OBLK   16                 // o's per block (8 warps x 2 o)
#define NOBLK  (OUT / OBLK)       // 128
#define GRID   (NCHUNK * NOBLK)   // 512
#define XSTR   516                // x_s row stride

// Scratch (device globals; reset in-kernel every call -> graph-replay safe)
__device__ float             g_h[HDIM];     // zero-init; reset by finisher
__device__ unsigned          g_ticket;      // reset by finisher
__device__ unsigned          g_done;        // reset by completion ticket
__device__ volatile unsigned g_flag;        // reset by completion ticket
__device__ float             g_alpha[KNUM];

// ---------------------------------------------------------------------------
// ONE kernel. Blocks 0..127 run the MLP phase (partial cond@w1 -> atomic g_h;
// ticket finisher: relu/w2/softmax -> g_alpha -> g_flag). Before spinning,
// EVERY block issues register-free prefetch.global.L2 covering its whole
// 256 KB kw region, so DRAM streams at full rate through the MLP window and
// the main loop's early quarters hit L2. Main body = R11's proven structure.
// ---------------------------------------------------------------------------
__global__ __launch_bounds__(256, 2) void fused_kernel(
        const float* __restrict__ x,     // [32, 2048]
        const float* __restrict__ cond,  // [1, 2048]
        const float* __restrict__ w1,    // [2048, 512]
        const float* __restrict__ b1,    // [512]
        const float* __restrict__ w2,    // [512, 8]
        const float* __restrict__ b2,    // [8]
        const float* __restrict__ kw,    // [8, 2048, 2048]
        const float* __restrict__ kb,    // [8, 2048]
        float* __restrict__ out) {       // [32, 2048]
    extern __shared__ float sm[];
    float* x_s    = sm;                  // 32 * 516 floats (~66 KB)
    float* h_s    = sm;                  // alias during MLP phase
    float* part_s = sm;                  // alias after compute
    __shared__ float    s_s[KNUM];
    __shared__ unsigned rank_s;

    int t    = threadIdx.x;
    int wid  = t >> 5;
    int lane = t & 31;
    int io   = lane & 15;
    int og   = lane >> 4;
    int ob   = blockIdx.x & (NOBLK - 1);          // 0..127
    int c    = blockIdx.x >> 7;                   // 0..3
    int i0   = c * IBLK;
    int oi   = wid * 2 + og;                      // 0..15
    int o    = ob * OBLK + oi;

    // ================= Phase A: MLP (blocks 0..127 only) =================
    if (blockIdx.x < 128) {
        int i0m = blockIdx.x * 16;
        float sA = 0.f, sB = 0.f;
#pragma unroll
        for (int i = 0; i < 16; ++i) {
            float cv = cond[i0m + i];
            sA += cv * w1[(i0m + i) * HDIM + t];
            sB += cv * w1[(i0m + i) * HDIM + t + 256];
        }
        atomicAdd(&g_h[t], sA);
        atomicAdd(&g_h[t + 256], sB);
        out[blockIdx.x * 512 + t]       = 0.f;    // zero out for epilogue adds
        out[blockIdx.x * 512 + t + 256] = 0.f;

        __threadfence();
        __syncthreads();
        if (t == 0) rank_s = atomicAdd(&g_ticket, 1u);
        __syncthreads();

        if (rank_s == 127) {              // finisher block
            __threadfence();
            h_s[t]       = fmaxf(g_h[t] + b1[t], 0.f);
            h_s[t + 256] = fmaxf(g_h[t + 256] + b1[t + 256], 0.f);
            g_h[t] = 0.f; g_h[t + 256] = 0.f;     // reset for next replay
            if (t == 0) g_ticket = 0;
            __syncthreads();

            if (wid < KNUM) {             // 8 warps, one score each
                float sc = 0.f;
#pragma unroll
                for (int m = 0; m < HDIM / 32; ++m) {
                    int jj = lane + m * 32;
                    sc += h_s[jj] * w2[jj * KNUM + wid];
                }
#pragma unroll
                for (int off = 16; off; off >>= 1)
                    sc += __shfl_xor_sync(FULL, sc, off);
                if (lane == 0) s_s[wid] = sc + b2[wid];
            }
            __syncthreads();              // h_s reads done before x staging
            if (t == 0) {
                float mx = -1e30f;
#pragma unroll
                for (int k = 0; k < KNUM; ++k) mx = fmaxf(mx, s_s[k]);
                float e[KNUM];
                float ssum = 0.f;
#pragma unroll
                for (int k = 0; k < KNUM; ++k) {
                    e[k] = __expf(s_s[k] - mx); ssum += e[k];
                }
                float inv = 1.f / ssum;
#pragma unroll
                for (int k = 0; k < KNUM; ++k) g_alpha[k] = e[k] * inv;
                __threadfence();
                g_flag = 1;               // release
            }
        }
    }

    // ====== Phase B: register-free L2 prefetch of the WHOLE kw region ======
    // Block region: 8 experts x 16 o x 2 KB rows = 2048 lines of 128 B.
    // 8 prefetches per thread; no destination regs, no scoreboard -> DRAM
    // streams through the MLP window instead of idling at the spin.
    {
        const char* kwb = reinterpret_cast<const char*>(kw);
#pragma unroll
        for (int j = 0; j < 8; ++j) {
            int e   = j * 256 + t;                // 0..2047 line index
            int row = e >> 4;                     // 0..127 = k*16 + ol
            int seg = e & 15;                     // 128B segment within 2KB row
            int k   = row >> 4;
            int ol  = row & 15;
            const char* p = kwb + ((size_t)k * KSZ +
                                   (size_t)(ob * OBLK + ol) * IN + i0) * 4 +
                            (size_t)seg * 128;
            asm volatile("prefetch.global.L2 [%0];" :: "l"(p));
        }
    }

    // issue quarter-0 register loads + x staging (also pre-spin DRAM work)
    const float* base = kw + (size_t)o * IN + i0 + io * 4;
    float4 cur[KNUM];
#pragma unroll
    for (int k = 0; k < KNUM; ++k)
        cur[k] = *reinterpret_cast<const float4*>(base + (size_t)k * KSZ);

    const float4* x4 = reinterpret_cast<const float4*>(x);
#pragma unroll
    for (int jj = 0; jj < (BATCH * IBLK) / (4 * 256); ++jj) {
        int idx = jj * 256 + t;                   // 0..4095 float4 units
        int b   = idx >> 7;                       // 128 f4 per row
        int il4 = idx & 127;
        *reinterpret_cast<float4*>(&x_s[b * XSTR + il4 * 4]) =
            x4[(b * IN + i0) / 4 + il4];
    }

    // spin: one thread polls, block parks at the barrier
    if (t == 0) {
        while (g_flag == 0) __nanosleep(128);
    }
    __syncthreads();
    __threadfence();                      // acquire side

    float a[KNUM];
#pragma unroll
    for (int k = 0; k < KNUM; ++k) a[k] = __ldcg(&g_alpha[k]);

    // ===================== Phase C: main loop (R11) =======================
    float acc[BATCH];
#pragma unroll
    for (int b = 0; b < BATCH; ++b) acc[b] = 0.f;

    for (int q = 0; q < NQ; ++q) {
        // aggregate experts into registers (consumes cur)
        float4 w4;
        w4.x = a[0] * cur[0].x; w4.y = a[0] * cur[0].y;
        w4.z = a[0] * cur[0].z; w4.w = a[0] * cur[0].w;
#pragma unroll
        for (int k = 1; k < KNUM; ++k) {
            float ak = a[k];
            w4.x += ak * cur[k].x; w4.y += ak * cur[k].y;
            w4.z += ak * cur[k].z; w4.w += ak * cur[k].w;
        }

        // prefetch next quarter into registers (hits L2 thanks to phase B)
        if (q < NQ - 1) {
            const float* nb = base + (q + 1) * 64;
#pragma unroll
            for (int k = 0; k < KNUM; ++k)
                cur[k] = *reinterpret_cast<const float4*>(nb + (size_t)k * KSZ);
        }

        // compute: full batch, 1 LDS.128 + 4 FMA per b (og-broadcast x)
        const float* xrow = x_s + q * 64 + io * 4;
#pragma unroll
        for (int b = 0; b < BATCH; ++b) {
            float4 xq = *reinterpret_cast<const float4*>(xrow + b * XSTR);
            acc[b] += w4.x * xq.x;
            acc[b] += w4.y * xq.y;
            acc[b] += w4.z * xq.z;
            acc[b] += w4.w * xq.w;
        }
    }

    // ============ epilogue: smem transpose-reduce + atomicAdd ============
    __syncthreads();                      // all warps done reading x_s
#pragma unroll
    for (int b = 0; b < BATCH; ++b)
        part_s[(b * 16 + oi) * 17 + io] = acc[b];
    __syncthreads();

#pragma unroll
    for (int r = 0; r < 2; ++r) {
        int e   = r * 256 + t;            // 0..511 = b*16 + oi2
        int b   = e >> 4;
        int oi2 = e & 15;
        const float* p = &part_s[e * 17];
        float s0 = 0.f, s1 = 0.f;
#pragma unroll
        for (int j = 0; j < 16; j += 2) { s0 += p[j]; s1 += p[j + 1]; }
        float v = s0 + s1;
        if (c == 0) {                     // fold aggregated bias once
            int o2 = ob * OBLK + oi2;
            float bb = 0.f;
#pragma unroll
            for (int k = 0; k < KNUM; ++k) bb += a[k] * kb[k * OUT + o2];
            v += bb;
        }
        atomicAdd(&out[b * OUT + ob * OBLK + oi2], v);
    }

    // ============ completion ticket: reset flag for next replay ==========
    __threadfence();
    __syncthreads();
    if (t == 0) {
        unsigned r = atomicAdd(&g_done, 1u);
        if (r == GRID - 1) {              // everyone is past the spin
            g_done = 0;
            g_flag = 0;
        }
    }
}

// ---------------------------------------------------------------------------
extern "C" void kernel_launch(void* const* d_in, const int* in_sizes, int n_in,
                              void* d_out, int out_size) {
    const float* x    = (const float*)d_in[0];
    const float* cond = (const float*)d_in[1];
    const float* w1   = (const float*)d_in[2];
    const float* b1   = (const float*)d_in[3];
    const float* w2   = (const float*)d_in[4];
    const float* b2   = (const float*)d_in[5];
    const float* kw   = (const float*)d_in[6];
    const float* kb   = (const float*)d_in[7];
    float* out = (float*)d_out;

    const int SMEM = (BATCH * XSTR) * 4;          // 66048 B
    static int smem_set = 0;
    if (!smem_set) {
        cudaFuncSetAttribute(fused_kernel,
                             cudaFuncAttributeMaxDynamicSharedMemorySize,
                             SMEM);
        smem_set = 1;
    }

    fused_kernel<<<GRID, 256, SMEM>>>(x, cond, w1, b1, w2, b2, kw, kb, out);
}

// round 17
// speedup vs baseline: 1.0793x; 1.0793x over previous
#include <cuda_runtime.h>

#define FULL 0xFFFFFFFFu

// Problem constants
#define BATCH 32
#define IN    2048
#define OUT   2048
#define KNUM  8
#define HDIM  512
#define KSZ   (IN * OUT)          // 4M elements per expert

#define IBLK   512                // i-range per block (8 quarters of 64)
#define NCHUNK (IN / IBLK)        // 4
#define NQ     (IBLK / 64)        // 8
#define OBLK   16                 // o's per block (8 warps x 2 o)
#define NOBLK  (OUT / OBLK)       // 128
#define GRID   (NCHUNK * NOBLK)   // 512
#define XSTR   516                // x_s row stride

// Scratch (device globals; reset/overwritten in-kernel -> graph-replay safe)
__device__ float             g_hp[128 * HDIM]; // partials; fully overwritten
__device__ unsigned          g_ticket;         // reset by finisher
__device__ unsigned          g_done;           // reset by completion ticket
__device__ volatile unsigned g_flag;           // reset by completion ticket
__device__ float             g_alpha[KNUM];

// ---------------------------------------------------------------------------
// ONE kernel. Blocks 0..127 run the MLP phase: contention-free partial
// stores of cond@w1 into g_hp (NO hot atomics — R14 profiling showed the
// 512-address atomic pileup was the 8-10us critical path), zero out-slice,
// ticket. Finisher block reduces the L2-hot partials (~1us), does
// relu/w2/softmax -> g_alpha, raises g_flag. ALL blocks issue quarter-0 kw
// loads + x staging BEFORE spinning. Main body = R11's proven structure.
// ---------------------------------------------------------------------------
__global__ __launch_bounds__(256, 2) void fused_kernel(
        const float* __restrict__ x,     // [32, 2048]
        const float* __restrict__ cond,  // [1, 2048]
        const float* __restrict__ w1,    // [2048, 512]
        const float* __restrict__ b1,    // [512]
        const float* __restrict__ w2,    // [512, 8]
        const float* __restrict__ b2,    // [8]
        const float* __restrict__ kw,    // [8, 2048, 2048]
        const float* __restrict__ kb,    // [8, 2048]
        float* __restrict__ out) {       // [32, 2048]
    extern __shared__ float sm[];
    float* x_s    = sm;                  // 32 * 516 floats (~66 KB)
    float* h_s    = sm;                  // alias during MLP phase (512 floats)
    float* part_s = sm;                  // alias after compute
    __shared__ float    s_s[KNUM];
    __shared__ unsigned rank_s;

    int t    = threadIdx.x;
    int wid  = t >> 5;
    int lane = t & 31;
    int io   = lane & 15;
    int og   = lane >> 4;
    int ob   = blockIdx.x & (NOBLK - 1);          // 0..127
    int c    = blockIdx.x >> 7;                   // 0..3
    int i0   = c * IBLK;
    int oi   = wid * 2 + og;                      // 0..15
    int o    = ob * OBLK + oi;

    // ================= Phase A: MLP (blocks 0..127 only) =================
    if (blockIdx.x < 128) {
        int i0m = blockIdx.x * 16;
        float sA = 0.f, sB = 0.f;
#pragma unroll
        for (int i = 0; i < 16; ++i) {
            float cv = cond[i0m + i];
            sA += cv * w1[(i0m + i) * HDIM + t];
            sB += cv * w1[(i0m + i) * HDIM + t + 256];
        }
        // contention-free partial stores (no atomics)
        g_hp[blockIdx.x * HDIM + t]       = sA;
        g_hp[blockIdx.x * HDIM + t + 256] = sB;
        out[blockIdx.x * 512 + t]       = 0.f;    // zero out for epilogue adds
        out[blockIdx.x * 512 + t + 256] = 0.f;

        __threadfence();
        __syncthreads();
        if (t == 0) rank_s = atomicAdd(&g_ticket, 1u);
        __syncthreads();

        if (rank_s == 127) {              // finisher block
            __threadfence();
            // reduce 128 partials for columns t and t+256 (coalesced, L2-hot)
            float hA[4] = {0.f, 0.f, 0.f, 0.f};
            float hB[4] = {0.f, 0.f, 0.f, 0.f};
#pragma unroll 8
            for (int p = 0; p < 128; p += 4) {
#pragma unroll
                for (int u = 0; u < 4; ++u) {
                    hA[u] += g_hp[(p + u) * HDIM + t];
                    hB[u] += g_hp[(p + u) * HDIM + t + 256];
                }
            }
            h_s[t]       = fmaxf((hA[0] + hA[1]) + (hA[2] + hA[3]) + b1[t], 0.f);
            h_s[t + 256] = fmaxf((hB[0] + hB[1]) + (hB[2] + hB[3]) + b1[t + 256], 0.f);
            if (t == 0) g_ticket = 0;     // reset for next replay
            __syncthreads();

            if (wid < KNUM) {             // 8 warps, one score each
                float sc = 0.f;
#pragma unroll
                for (int m = 0; m < HDIM / 32; ++m) {
                    int jj = lane + m * 32;
                    sc += h_s[jj] * w2[jj * KNUM + wid];
                }
#pragma unroll
                for (int off = 16; off; off >>= 1)
                    sc += __shfl_xor_sync(FULL, sc, off);
                if (lane == 0) s_s[wid] = sc + b2[wid];
            }
            __syncthreads();              // h_s reads done before x staging
            if (t == 0) {
                float mx = -1e30f;
#pragma unroll
                for (int k = 0; k < KNUM; ++k) mx = fmaxf(mx, s_s[k]);
                float e[KNUM];
                float ssum = 0.f;
#pragma unroll
                for (int k = 0; k < KNUM; ++k) {
                    e[k] = __expf(s_s[k] - mx); ssum += e[k];
                }
                float inv = 1.f / ssum;
#pragma unroll
                for (int k = 0; k < KNUM; ++k) g_alpha[k] = e[k] * inv;
                __threadfence();
                g_flag = 1;               // release
            }
        }
    }

    // ======= Phase B: issue alpha-independent DRAM work, THEN spin =======
    const float* base = kw + (size_t)o * IN + i0 + io * 4;
    float4 cur[KNUM];
#pragma unroll
    for (int k = 0; k < KNUM; ++k)
        cur[k] = *reinterpret_cast<const float4*>(base + (size_t)k * KSZ);

    // stage x tile: x_s[b][il] = x[b][i0+il]
    const float4* x4 = reinterpret_cast<const float4*>(x);
#pragma unroll
    for (int jj = 0; jj < (BATCH * IBLK) / (4 * 256); ++jj) {
        int idx = jj * 256 + t;                   // 0..4095 float4 units
        int b   = idx >> 7;                       // 128 f4 per row
        int il4 = idx & 127;
        *reinterpret_cast<float4*>(&x_s[b * XSTR + il4 * 4]) =
            x4[(b * IN + i0) / 4 + il4];
    }

    // spin: one thread polls, block parks at the barrier
    if (t == 0) {
        while (g_flag == 0) __nanosleep(64);
    }
    __syncthreads();
    __threadfence();                      // acquire side

    float a[KNUM];
#pragma unroll
    for (int k = 0; k < KNUM; ++k) a[k] = __ldcg(&g_alpha[k]);

    // ===================== Phase C: main loop (R11) =======================
    float acc[BATCH];
#pragma unroll
    for (int b = 0; b < BATCH; ++b) acc[b] = 0.f;

    for (int q = 0; q < NQ; ++q) {
        // aggregate experts into registers (consumes cur)
        float4 w4;
        w4.x = a[0] * cur[0].x; w4.y = a[0] * cur[0].y;
        w4.z = a[0] * cur[0].z; w4.w = a[0] * cur[0].w;
#pragma unroll
        for (int k = 1; k < KNUM; ++k) {
            float ak = a[k];
            w4.x += ak * cur[k].x; w4.y += ak * cur[k].y;
            w4.z += ak * cur[k].z; w4.w += ak * cur[k].w;
        }

        // prefetch next quarter (lands during this quarter's compute)
        if (q < NQ - 1) {
            const float* nb = base + (q + 1) * 64;
#pragma unroll
            for (int k = 0; k < KNUM; ++k)
                cur[k] = *reinterpret_cast<const float4*>(nb + (size_t)k * KSZ);
        }

        // compute: full batch, 1 LDS.128 + 4 FMA per b (og-broadcast x)
        const float* xrow = x_s + q * 64 + io * 4;
#pragma unroll
        for (int b = 0; b < BATCH; ++b) {
            float4 xq = *reinterpret_cast<const float4*>(xrow + b * XSTR);
            acc[b] += w4.x * xq.x;
            acc[b] += w4.y * xq.y;
            acc[b] += w4.z * xq.z;
            acc[b] += w4.w * xq.w;
        }
    }

    // ============ epilogue: smem transpose-reduce + atomicAdd ============
    __syncthreads();                      // all warps done reading x_s
#pragma unroll
    for (int b = 0; b < BATCH; ++b)
        part_s[(b * 16 + oi) * 17 + io] = acc[b];
    __syncthreads();

#pragma unroll
    for (int r = 0; r < 2; ++r) {
        int e   = r * 256 + t;            // 0..511 = b*16 + oi2
        int b   = e >> 4;
        int oi2 = e & 15;
        const float* p = &part_s[e * 17];
        float s0 = 0.f, s1 = 0.f;
#pragma unroll
        for (int j = 0; j < 16; j += 2) { s0 += p[j]; s1 += p[j + 1]; }
        float v = s0 + s1;
        if (c == 0) {                     // fold aggregated bias once
            int o2 = ob * OBLK + oi2;
            float bb = 0.f;
#pragma unroll
            for (int k = 0; k < KNUM; ++k) bb += a[k] * kb[k * OUT + o2];
            v += bb;
        }
        atomicAdd(&out[b * OUT + ob * OBLK + oi2], v);
    }

    // ============ completion ticket: reset flag for next replay ==========
    __threadfence();
    __syncthreads();
    if (t == 0) {
        unsigned r = atomicAdd(&g_done, 1u);
        if (r == GRID - 1) {              // everyone is past the spin
            g_done = 0;
            g_flag = 0;
        }
    }
}

// ---------------------------------------------------------------------------
extern "C" void kernel_launch(void* const* d_in, const int* in_sizes, int n_in,
                              void* d_out, int out_size) {
    const float* x    = (const float*)d_in[0];
    const float* cond = (const float*)d_in[1];
    const float* w1   = (const float*)d_in[2];
    const float* b1   = (const float*)d_in[3];
    const float* w2   = (const float*)d_in[4];
    const float* b2   = (const float*)d_in[5];
    const float* kw   = (const float*)d_in[6];
    const float* kb   = (const float*)d_in[7];
    float* out = (float*)d_out;

    const int SMEM = (BATCH * XSTR) * 4;          // 66048 B
    static int smem_set = 0;
    if (!smem_set) {
        cudaFuncSetAttribute(fused_kernel,
                             cudaFuncAttributeMaxDynamicSharedMemorySize,
                             SMEM);
        smem_set = 1;
    }

    fused_kernel<<<GRID, 256, SMEM>>>(x, cond, w1, b1, w2, b2, kw, kb, out);
}